// round 2
// baseline (speedup 1.0000x reference)
#include <cuda_runtime.h>

#define LDIM 32
#define VOL (32*32*32*32)

// Wilson Dslash, DeGrand-Rossi basis, spin-projection (half-spinor) form.
// psi: [V][4][3] re/im separate. U: [V][4][3][3] re/im separate.
// out: res_re at [0, V*12), res_im at [V*12, 2*V*12).

template<int MU, int FWD>
__device__ __forceinline__ void hop(int nbr, int usite,
                                    const float* __restrict__ pr, const float* __restrict__ pi,
                                    const float* __restrict__ ur, const float* __restrict__ ui,
                                    float rr[12], float ri[12])
{
    // ---- load neighbor spinor (12 complex), vectorized float4 ----
    float vr[12], vi[12];
    {
        const float4* p4 = reinterpret_cast<const float4*>(pr + (size_t)nbr * 12);
        float4 a = __ldg(p4 + 0), b = __ldg(p4 + 1), c = __ldg(p4 + 2);
        vr[0]=a.x; vr[1]=a.y; vr[2]=a.z; vr[3]=a.w;
        vr[4]=b.x; vr[5]=b.y; vr[6]=b.z; vr[7]=b.w;
        vr[8]=c.x; vr[9]=c.y; vr[10]=c.z; vr[11]=c.w;
    }
    {
        const float4* p4 = reinterpret_cast<const float4*>(pi + (size_t)nbr * 12);
        float4 a = __ldg(p4 + 0), b = __ldg(p4 + 1), c = __ldg(p4 + 2);
        vi[0]=a.x; vi[1]=a.y; vi[2]=a.z; vi[3]=a.w;
        vi[4]=b.x; vi[5]=b.y; vi[6]=b.z; vi[7]=b.w;
        vi[8]=c.x; vi[9]=c.y; vi[10]=c.z; vi[11]=c.w;
    }

    // ---- spin projection: h0 (hr[0..2]), h1 (hr[3..5]) ----
    // v0=v[c], v1=v[3+c], v2=v[6+c], v3=v[9+c]
    float hr[6], hi[6];
#pragma unroll
    for (int c = 0; c < 3; ++c) {
        if (FWD) { // Pm = 1 - gamma_mu
            if (MU == 0) { // h0 = v0 - i v3 ; h1 = v1 - i v2
                hr[c]   = vr[c]   + vi[9+c]; hi[c]   = vi[c]   - vr[9+c];
                hr[3+c] = vr[3+c] + vi[6+c]; hi[3+c] = vi[3+c] - vr[6+c];
            } else if (MU == 1) { // h0 = v0 + v3 ; h1 = v1 - v2
                hr[c]   = vr[c]   + vr[9+c]; hi[c]   = vi[c]   + vi[9+c];
                hr[3+c] = vr[3+c] - vr[6+c]; hi[3+c] = vi[3+c] - vi[6+c];
            } else if (MU == 2) { // h0 = v0 - i v2 ; h1 = v1 + i v3
                hr[c]   = vr[c]   + vi[6+c]; hi[c]   = vi[c]   - vr[6+c];
                hr[3+c] = vr[3+c] - vi[9+c]; hi[3+c] = vi[3+c] + vr[9+c];
            } else { // h0 = v0 - v2 ; h1 = v1 - v3
                hr[c]   = vr[c]   - vr[6+c]; hi[c]   = vi[c]   - vi[6+c];
                hr[3+c] = vr[3+c] - vr[9+c]; hi[3+c] = vi[3+c] - vi[9+c];
            }
        } else { // Pp = 1 + gamma_mu
            if (MU == 0) { // h0 = v0 + i v3 ; h1 = v1 + i v2
                hr[c]   = vr[c]   - vi[9+c]; hi[c]   = vi[c]   + vr[9+c];
                hr[3+c] = vr[3+c] - vi[6+c]; hi[3+c] = vi[3+c] + vr[6+c];
            } else if (MU == 1) { // h0 = v0 - v3 ; h1 = v1 + v2
                hr[c]   = vr[c]   - vr[9+c]; hi[c]   = vi[c]   - vi[9+c];
                hr[3+c] = vr[3+c] + vr[6+c]; hi[3+c] = vi[3+c] + vi[6+c];
            } else if (MU == 2) { // h0 = v0 + i v2 ; h1 = v1 - i v3
                hr[c]   = vr[c]   - vi[6+c]; hi[c]   = vi[c]   + vr[6+c];
                hr[3+c] = vr[3+c] + vi[9+c]; hi[3+c] = vi[3+c] - vr[9+c];
            } else { // h0 = v0 + v2 ; h1 = v1 + v3
                hr[c]   = vr[c]   + vr[6+c]; hi[c]   = vi[c]   + vi[6+c];
                hr[3+c] = vr[3+c] + vr[9+c]; hi[3+c] = vi[3+c] + vi[9+c];
            }
        }
    }

    // ---- color multiply: a = U h (fwd) or U^dag h (bwd) ----
    size_t ub = ((size_t)usite * 4 + MU) * 9;
    float ar[6] = {0,0,0,0,0,0}, ai[6] = {0,0,0,0,0,0};
#pragma unroll
    for (int i = 0; i < 3; ++i) {
#pragma unroll
        for (int j = 0; j < 3; ++j) {
            float urr, uii;
            if (FWD) {
                urr = __ldg(ur + ub + i*3 + j);
                uii = __ldg(ui + ub + i*3 + j);
            } else {
                urr =  __ldg(ur + ub + j*3 + i);
                uii = -__ldg(ui + ub + j*3 + i);
            }
            ar[i]   += urr*hr[j]   - uii*hi[j];
            ai[i]   += urr*hi[j]   + uii*hr[j];
            ar[3+i] += urr*hr[3+j] - uii*hi[3+j];
            ai[3+i] += urr*hi[3+j] + uii*hr[3+j];
        }
    }

    // ---- reconstruct: rows 0,1 always a0,a1; rows 2,3 per-mu phase ----
#pragma unroll
    for (int c = 0; c < 3; ++c) {
        rr[c]   += ar[c];   ri[c]   += ai[c];
        rr[3+c] += ar[3+c]; ri[3+c] += ai[3+c];
        if (FWD) {
            if (MU == 0) { // r2 += i a1 ; r3 += i a0
                rr[6+c] -= ai[3+c]; ri[6+c] += ar[3+c];
                rr[9+c] -= ai[c];   ri[9+c] += ar[c];
            } else if (MU == 1) { // r2 -= a1 ; r3 += a0
                rr[6+c] -= ar[3+c]; ri[6+c] -= ai[3+c];
                rr[9+c] += ar[c];   ri[9+c] += ai[c];
            } else if (MU == 2) { // r2 += i a0 ; r3 -= i a1
                rr[6+c] -= ai[c];   ri[6+c] += ar[c];
                rr[9+c] += ai[3+c]; ri[9+c] -= ar[3+c];
            } else { // r2 -= a0 ; r3 -= a1
                rr[6+c] -= ar[c];   ri[6+c] -= ai[c];
                rr[9+c] -= ar[3+c]; ri[9+c] -= ai[3+c];
            }
        } else {
            if (MU == 0) { // r2 -= i a1 ; r3 -= i a0
                rr[6+c] += ai[3+c]; ri[6+c] -= ar[3+c];
                rr[9+c] += ai[c];   ri[9+c] -= ar[c];
            } else if (MU == 1) { // r2 += a1 ; r3 -= a0
                rr[6+c] += ar[3+c]; ri[6+c] += ai[3+c];
                rr[9+c] -= ar[c];   ri[9+c] -= ai[c];
            } else if (MU == 2) { // r2 -= i a0 ; r3 += i a1
                rr[6+c] += ai[c];   ri[6+c] -= ar[c];
                rr[9+c] -= ai[3+c]; ri[9+c] += ar[3+c];
            } else { // r2 += a0 ; r3 += a1
                rr[6+c] += ar[c];   ri[6+c] += ai[c];
                rr[9+c] += ar[3+c]; ri[9+c] += ai[3+c];
            }
        }
    }
}

__global__ void __launch_bounds__(256)
dslash_kernel(const float* __restrict__ psi_re, const float* __restrict__ psi_im,
              const float* __restrict__ U_re,  const float* __restrict__ U_im,
              float* __restrict__ out_re, float* __restrict__ out_im)
{
    int site = blockIdx.x * 256 + threadIdx.x;
    int x3 =  site        & 31;
    int x2 = (site >> 5)  & 31;
    int x1 = (site >> 10) & 31;
    int x0 = (site >> 15) & 31;

    float rr[12], ri[12];
#pragma unroll
    for (int k = 0; k < 12; ++k) { rr[k] = 0.f; ri[k] = 0.f; }

    // strides per direction in linear (site) index
    const int S0 = 32768, S1 = 1024, S2 = 32, S3 = 1;

    int fw0 = (x0 < 31) ? site + S0 : site - 31*S0;
    int bw0 = (x0 > 0)  ? site - S0 : site + 31*S0;
    int fw1 = (x1 < 31) ? site + S1 : site - 31*S1;
    int bw1 = (x1 > 0)  ? site - S1 : site + 31*S1;
    int fw2 = (x2 < 31) ? site + S2 : site - 31*S2;
    int bw2 = (x2 > 0)  ? site - S2 : site + 31*S2;
    int fw3 = (x3 < 31) ? site + S3 : site - 31*S3;
    int bw3 = (x3 > 0)  ? site - S3 : site + 31*S3;

    hop<0,1>(fw0, site, psi_re, psi_im, U_re, U_im, rr, ri);
    hop<0,0>(bw0, bw0,  psi_re, psi_im, U_re, U_im, rr, ri);
    hop<1,1>(fw1, site, psi_re, psi_im, U_re, U_im, rr, ri);
    hop<1,0>(bw1, bw1,  psi_re, psi_im, U_re, U_im, rr, ri);
    hop<2,1>(fw2, site, psi_re, psi_im, U_re, U_im, rr, ri);
    hop<2,0>(bw2, bw2,  psi_re, psi_im, U_re, U_im, rr, ri);
    hop<3,1>(fw3, site, psi_re, psi_im, U_re, U_im, rr, ri);
    hop<3,0>(bw3, bw3,  psi_re, psi_im, U_re, U_im, rr, ri);

    // ---- store: res = -0.5 * accum ----
    float4* o4r = reinterpret_cast<float4*>(out_re + (size_t)site * 12);
    float4* o4i = reinterpret_cast<float4*>(out_im + (size_t)site * 12);
    float4 t;
    t.x = -0.5f*rr[0]; t.y = -0.5f*rr[1]; t.z = -0.5f*rr[2];  t.w = -0.5f*rr[3];  o4r[0] = t;
    t.x = -0.5f*rr[4]; t.y = -0.5f*rr[5]; t.z = -0.5f*rr[6];  t.w = -0.5f*rr[7];  o4r[1] = t;
    t.x = -0.5f*rr[8]; t.y = -0.5f*rr[9]; t.z = -0.5f*rr[10]; t.w = -0.5f*rr[11]; o4r[2] = t;
    t.x = -0.5f*ri[0]; t.y = -0.5f*ri[1]; t.z = -0.5f*ri[2];  t.w = -0.5f*ri[3];  o4i[0] = t;
    t.x = -0.5f*ri[4]; t.y = -0.5f*ri[5]; t.z = -0.5f*ri[6];  t.w = -0.5f*ri[7];  o4i[1] = t;
    t.x = -0.5f*ri[8]; t.y = -0.5f*ri[9]; t.z = -0.5f*ri[10]; t.w = -0.5f*ri[11]; o4i[2] = t;
}

extern "C" void kernel_launch(void* const* d_in, const int* in_sizes, int n_in,
                              void* d_out, int out_size)
{
    const float* psi_re = (const float*)d_in[0];
    const float* psi_im = (const float*)d_in[1];
    const float* U_re   = (const float*)d_in[2];
    const float* U_im   = (const float*)d_in[3];
    // d_in[4..7] are the projector matrices; algebra is hardcoded (they are
    // the fixed DeGrand-Rossi 1 -/+ gamma_mu projectors).

    float* out_re = (float*)d_out;
    float* out_im = out_re + (size_t)VOL * 12;

    dslash_kernel<<<VOL / 256, 256>>>(psi_re, psi_im, U_re, U_im, out_re, out_im);
}